// round 1
// baseline (speedup 1.0000x reference)
#include <cuda_runtime.h>
#include <cuda_bf16.h>
#include <math.h>

// Problem constants (fixed by reference setup_inputs)
#define NPTS 4096
#define DIM  1024
#define MCLS 8
#define NPOSD 7               // M-1 positives per row
#define NNEGD 4088            // N-M negatives per row
#define KSEL 17               // threshold = 17th smallest (1-based) of 4095 non-self dists
#define ALPHA_C 30.0f
#define OFF_POS 4
#define OFF_NEG (4 + NPTS * NPOSD)

// GEMM tiling
#define BM 128
#define BN 128
#define BK 16
#define NB (NPTS / BM)        // 32

// ---------------------------------------------------------------------------
// Device-global scratch (no allocations allowed)
// ---------------------------------------------------------------------------
__device__ float g_sq[NPTS];
__device__ float g_loss[NPTS];
__device__ float g_psum[NPTS];
__device__ float g_nsum[NPTS];

// ---------------------------------------------------------------------------
// Helpers
// ---------------------------------------------------------------------------
__device__ __forceinline__ unsigned long long pack2(float x, float y) {
    unsigned long long r;
    asm("mov.b64 %0, {%1, %2};" : "=l"(r) : "f"(x), "f"(y));
    return r;
}
__device__ __forceinline__ void unpack2(unsigned long long p, float& lo, float& hi) {
    asm("mov.b64 {%0, %1}, %2;" : "=f"(lo), "=f"(hi) : "l"(p));
}
// Blackwell packed f32x2 FMA: 2 fp32 FMAs per issue slot (ptxas never emits this
// from C++; FFMA-3reg is rt=2/SMSP, so this ~doubles SGEMM throughput).
__device__ __forceinline__ void fma2(unsigned long long& c, unsigned long long a,
                                     unsigned long long b) {
    asm("fma.rn.f32x2 %0, %1, %2, %3;" : "=l"(c) : "l"(a), "l"(b), "l"(c));
}

// exp(a) via degree-7 polynomial exp2 (rel err ~5e-9), avoids MUFU throughput wall.
__device__ __forceinline__ float fast_exp(float a) {
    float y = a * 1.4426950408889634f;          // a * log2(e)
    float n = rintf(y);
    float f = y - n;                            // f in [-0.5, 0.5]
    float p = 1.525273380405984e-5f;
    p = fmaf(p, f, 1.540353039338161e-4f);
    p = fmaf(p, f, 1.333355814642844e-3f);
    p = fmaf(p, f, 9.618129107628477e-3f);
    p = fmaf(p, f, 5.550410866482158e-2f);
    p = fmaf(p, f, 2.402265069591007e-1f);
    p = fmaf(p, f, 6.931471805599453e-1f);
    p = fmaf(p, f, 1.0f);
    int e = (int)n;                             // |a|<=30 -> e in [-44,44], always valid
    return p * __int_as_float((e + 127) << 23);
}

// Flat index into d_out for dist(i, j), j != i.
// Output layout (flattened reference tuple):
//   [0]=loss [1]=accuracy [2]=pos_d [3]=neg_d [4 .. 4+N*7)=pos_dist [..]=neg_dist
__device__ __forceinline__ int out_index(int i, int j) {
    int lo = (i >> 3) << 3;                     // class block start
    unsigned rel = (unsigned)(j - lo);
    if (rel < 8u) {                             // positive (j != i guaranteed by caller)
        int p = j - lo - (j > i ? 1 : 0);
        return OFF_POS + i * NPOSD + p;
    }
    int p = (j < lo) ? j : (j - 8);
    return OFF_NEG + i * NNEGD + p;
}

// Block-wide sum over 256 threads (deterministic tree).
__device__ __forceinline__ float block_sum256(float v, float* buf) {
    int t = threadIdx.x;
#pragma unroll
    for (int d = 16; d > 0; d >>= 1) v += __shfl_down_sync(0xFFFFFFFFu, v, d);
    if ((t & 31) == 0) buf[t >> 5] = v;
    __syncthreads();
    if (t < 32) {
        float x = (t < 8) ? buf[t] : 0.0f;
#pragma unroll
        for (int d = 4; d > 0; d >>= 1) x += __shfl_down_sync(0xFFFFFFFFu, x, d);
        if (t == 0) buf[0] = x;
    }
    __syncthreads();
    float r = buf[0];
    __syncthreads();
    return r;
}

__device__ __forceinline__ float block_min256(float v, float* buf) {
    int t = threadIdx.x;
#pragma unroll
    for (int d = 16; d > 0; d >>= 1) v = fminf(v, __shfl_down_sync(0xFFFFFFFFu, v, d));
    if ((t & 31) == 0) buf[t >> 5] = v;
    __syncthreads();
    if (t < 32) {
        float x = (t < 8) ? buf[t] : __int_as_float(0x7f800000);
#pragma unroll
        for (int d = 4; d > 0; d >>= 1) x = fminf(x, __shfl_down_sync(0xFFFFFFFFu, x, d));
        if (t == 0) buf[0] = x;
    }
    __syncthreads();
    float r = buf[0];
    __syncthreads();
    return r;
}

// ---------------------------------------------------------------------------
// Kernel 1: row squared norms
// ---------------------------------------------------------------------------
__global__ __launch_bounds__(256) void sq_kernel(const float* __restrict__ X) {
    int i = blockIdx.x, t = threadIdx.x;
    const float4* row = (const float4*)(X + (size_t)i * DIM);
    float4 x = row[t];                           // DIM/4 == 256 == blockDim
    float s = fmaf(x.x, x.x, fmaf(x.y, x.y, fmaf(x.z, x.z, x.w * x.w)));
    __shared__ float rbuf[8];
    s = block_sum256(s, rbuf);
    if (t == 0) g_sq[i] = s;
}

// ---------------------------------------------------------------------------
// Kernel 2: symmetric SGEMM (f32x2 packed FMA) with fused dist epilogue that
// scatters directly into the pos/neg sections of d_out. Only upper-triangular
// block pairs are computed; off-diagonal tiles write both (i,j) and (j,i).
// ---------------------------------------------------------------------------
__global__ __launch_bounds__(256, 2) void gemm_dist_kernel(const float* __restrict__ X,
                                                           float* __restrict__ out) {
    __shared__ __align__(16) float As[BK][BM];
    __shared__ __align__(16) float Bs[BK][BN];

    // decode blockIdx -> (bi <= bj)
    int b = blockIdx.x;
    int bi = 0, rem = b;
    while (rem >= NB - bi) { rem -= NB - bi; bi++; }
    int bj = bi + rem;

    int t = threadIdx.x;
    int tx = t & 15, ty = t >> 4;

    unsigned long long acc[8][4];
#pragma unroll
    for (int m = 0; m < 8; m++)
#pragma unroll
        for (int n = 0; n < 4; n++) acc[m][n] = 0ull;

    const float* Ap = X + (size_t)bi * BM * DIM;
    const float* Bp = X + (size_t)bj * BM * DIM;
    int lr = t >> 2;            // 0..63
    int lc = (t & 3) << 2;      // 0,4,8,12

    for (int k0 = 0; k0 < DIM; k0 += BK) {
#pragma unroll
        for (int h = 0; h < 2; h++) {
            int r = lr + h * 64;
            float4 va = *(const float4*)(Ap + (size_t)r * DIM + k0 + lc);
            As[lc + 0][r] = va.x; As[lc + 1][r] = va.y;
            As[lc + 2][r] = va.z; As[lc + 3][r] = va.w;
            float4 vb = *(const float4*)(Bp + (size_t)r * DIM + k0 + lc);
            Bs[lc + 0][r] = vb.x; Bs[lc + 1][r] = vb.y;
            Bs[lc + 2][r] = vb.z; Bs[lc + 3][r] = vb.w;
        }
        __syncthreads();
#pragma unroll
        for (int kk = 0; kk < BK; kk++) {
            float4 a0 = *(const float4*)&As[kk][ty * 8];
            float4 a1 = *(const float4*)&As[kk][ty * 8 + 4];
            ulonglong2 b0 = *(const ulonglong2*)&Bs[kk][tx * 8];
            ulonglong2 b1 = *(const ulonglong2*)&Bs[kk][tx * 8 + 4];
            unsigned long long bp[4] = {b0.x, b0.y, b1.x, b1.y};
            float am[8] = {a0.x, a0.y, a0.z, a0.w, a1.x, a1.y, a1.z, a1.w};
#pragma unroll
            for (int m = 0; m < 8; m++) {
                unsigned long long ap = pack2(am[m], am[m]);
#pragma unroll
                for (int n = 0; n < 4; n++) fma2(acc[m][n], ap, bp[n]);
            }
        }
        __syncthreads();
    }

    int gi0 = bi * BM + ty * 8;
    int gj0 = bj * BN + tx * 8;
#pragma unroll
    for (int m = 0; m < 8; m++) {
        int gi = gi0 + m;
        float sqi = g_sq[gi];
#pragma unroll
        for (int n2 = 0; n2 < 4; n2++) {
            float c0, c1;
            unpack2(acc[m][n2], c0, c1);
            int gj = gj0 + n2 * 2;
            float d0 = sqrtf(fmaxf(sqi + g_sq[gj]     - 2.0f * c0, 1e-12f));
            float d1 = sqrtf(fmaxf(sqi + g_sq[gj + 1] - 2.0f * c1, 1e-12f));
            if (bi == bj) {
                if (gi != gj)     out[out_index(gi, gj)]     = d0;
                if (gi != gj + 1) out[out_index(gi, gj + 1)] = d1;
            } else {
                out[out_index(gi, gj)]     = d0;
                out[out_index(gj, gi)]     = d0;
                out[out_index(gi, gj + 1)] = d1;
                out[out_index(gj + 1, gi)] = d1;
            }
        }
    }
}

// ---------------------------------------------------------------------------
// Kernel 3: per-row exact 17th-smallest via bitwise radix select, then logits.
// One block (256 threads) per row; the row's 4095 dists live in registers.
// ---------------------------------------------------------------------------
__global__ __launch_bounds__(256) void row_select_kernel(const float* __restrict__ out) {
    int i = blockIdx.x;
    int t = threadIdx.x;
    const float* pos = out + OFF_POS + i * NPOSD;
    const float* neg = out + OFF_NEG + (size_t)i * NNEGD;

    float v[16];
    float psum = 0.0f, nsum = 0.0f;
    float minpos = __int_as_float(0x7f800000);
#pragma unroll
    for (int s = 0; s < 16; s++) {
        int idx = t + (s << 8);                  // 0..4095 ; 4095 is padding
        float val;
        if (idx < NPOSD) {
            val = pos[idx];
            psum += val;
            minpos = fminf(minpos, val);
        } else if (idx < NPOSD + NNEGD) {
            val = neg[idx - NPOSD];
            nsum += val;
        } else {
            val = __int_as_float(0x7f800000);    // +inf sorts last
        }
        v[s] = val;
    }

    // exact radix select: k-th smallest bit pattern (all values positive floats)
    __shared__ int hist[256];
    __shared__ int wsum[8];
    __shared__ int sel[2];
    unsigned prefix = 0u;
    int k = KSEL;
#pragma unroll
    for (int pass = 0; pass < 4; pass++) {
        int shift = 24 - pass * 8;
        hist[t] = 0;
        __syncthreads();
        unsigned pm = (pass == 0) ? 0u : (0xFFFFFFFFu << (shift + 8));
#pragma unroll
        for (int s = 0; s < 16; s++) {
            unsigned bbits = __float_as_uint(v[s]);
            if ((bbits & pm) == prefix) atomicAdd(&hist[(bbits >> shift) & 255u], 1);
        }
        __syncthreads();
        int cnt = hist[t];
        int x = cnt;
#pragma unroll
        for (int d2 = 1; d2 < 32; d2 <<= 1) {
            int y = __shfl_up_sync(0xFFFFFFFFu, x, d2);
            if ((t & 31) >= d2) x += y;
        }
        if ((t & 31) == 31) wsum[t >> 5] = x;
        __syncthreads();
        if (t < 8) {
            int y = wsum[t];
#pragma unroll
            for (int d2 = 1; d2 < 8; d2 <<= 1) {
                int z = __shfl_up_sync(0xFFu, y, d2);
                if (t >= d2) y += z;
            }
            wsum[t] = y;
        }
        __syncthreads();
        int incl = x + ((t >= 32) ? wsum[(t >> 5) - 1] : 0);
        int excl = incl - cnt;
        if (incl >= k && excl < k) { sel[0] = t; sel[1] = excl; }
        __syncthreads();
        prefix |= ((unsigned)sel[0]) << shift;
        k -= sel[1];
        __syncthreads();
    }
    float thr = __uint_as_float(prefix);         // exact 17th smallest

    // logits: strict d < thr, matching the reference
    float pe = 0.0f, ne = 0.0f;
#pragma unroll
    for (int s = 0; s < 16; s++) {
        int idx = t + (s << 8);
        float d = v[s];
        if (idx < NPOSD + NNEGD && d < thr) {
            float e = fast_exp(ALPHA_C * (1.0f - d));
            if (idx < NPOSD) pe += e; else ne += e;
        }
    }

    __shared__ float rbuf[8];
    pe     = block_sum256(pe, rbuf);
    ne     = block_sum256(ne, rbuf);
    psum   = block_sum256(psum, rbuf);
    nsum   = block_sum256(nsum, rbuf);
    minpos = block_min256(minpos, rbuf);

    if (t == 0) {
        float pl = (minpos < thr) ? pe : fast_exp(ALPHA_C * (1.0f - minpos));
        float loss = logf(pl + ne) - logf(pl);
        g_loss[i] = loss;
        g_psum[i] = psum;
        g_nsum[i] = nsum;
    }
}

// ---------------------------------------------------------------------------
// Kernel 4: deterministic final reduction -> 4 scalars
// ---------------------------------------------------------------------------
__global__ __launch_bounds__(256) void final_kernel(float* __restrict__ out) {
    int t = threadIdx.x;
    float ls = 0.0f, ac = 0.0f, ps = 0.0f, ns = 0.0f;
    for (int j = t; j < NPTS; j += 256) {
        float l = g_loss[j];
        ls += l;
        ac += (l < 0.6f) ? 1.0f : 0.0f;
        ps += g_psum[j];
        ns += g_nsum[j];
    }
    __shared__ float rbuf[8];
    ls = block_sum256(ls, rbuf);
    ac = block_sum256(ac, rbuf);
    ps = block_sum256(ps, rbuf);
    ns = block_sum256(ns, rbuf);
    if (t == 0) {
        out[0] = ls / (float)NPTS;
        out[1] = ac / (float)NPTS;
        out[2] = ps / ((float)NPTS * (float)NPOSD);
        out[3] = ns / ((float)NPTS * (float)NNEGD);
    }
}

// ---------------------------------------------------------------------------
// Launch
// ---------------------------------------------------------------------------
extern "C" void kernel_launch(void* const* d_in, const int* in_sizes, int n_in,
                              void* d_out, int out_size) {
    const float* X = (const float*)d_in[0];
    float* out = (float*)d_out;
    (void)in_sizes; (void)n_in; (void)out_size;

    sq_kernel<<<NPTS, 256>>>(X);
    gemm_dist_kernel<<<NB * (NB + 1) / 2, 256>>>(X, out);
    row_select_kernel<<<NPTS, 256>>>(out);
    final_kernel<<<1, 256>>>(out);
}

// round 2
// speedup vs baseline: 1.0004x; 1.0004x over previous
#include <cuda_runtime.h>
#include <cuda_bf16.h>
#include <math.h>

// Problem constants (fixed by reference setup_inputs)
#define NPTS 4096
#define DIM  1024
#define MCLS 8
#define NPOSD 7               // M-1 positives per row
#define NNEGD 4088            // N-M negatives per row
#define KSEL 17               // threshold = 17th smallest (1-based) of 4095 non-self dists
#define ALPHA_C 30.0f
#define OFF_POS 4
#define OFF_NEG (4 + NPTS * NPOSD)

// GEMM tiling
#define BM 128
#define BN 128
#define BK 16
#define NB (NPTS / BM)        // 32

// ---------------------------------------------------------------------------
// Device-global scratch (no allocations allowed)
// ---------------------------------------------------------------------------
__device__ float g_sq[NPTS];
__device__ float g_loss[NPTS];
__device__ float g_psum[NPTS];
__device__ float g_nsum[NPTS];

// ---------------------------------------------------------------------------
// Helpers
// ---------------------------------------------------------------------------
__device__ __forceinline__ unsigned long long pack2(float x, float y) {
    unsigned long long r;
    asm("mov.b64 %0, {%1, %2};" : "=l"(r) : "f"(x), "f"(y));
    return r;
}
__device__ __forceinline__ void unpack2(unsigned long long p, float& lo, float& hi) {
    asm("mov.b64 {%0, %1}, %2;" : "=f"(lo), "=f"(hi) : "l"(p));
}
// Blackwell packed f32x2 FMA: 2 fp32 FMAs per issue slot (ptxas never emits this
// from C++; FFMA-3reg is rt=2/SMSP, so this ~doubles SGEMM throughput).
__device__ __forceinline__ void fma2(unsigned long long& c, unsigned long long a,
                                     unsigned long long b) {
    asm("fma.rn.f32x2 %0, %1, %2, %3;" : "=l"(c) : "l"(a), "l"(b), "l"(c));
}

// exp(a) via degree-7 polynomial exp2 (rel err ~5e-9), avoids MUFU throughput wall.
__device__ __forceinline__ float fast_exp(float a) {
    float y = a * 1.4426950408889634f;          // a * log2(e)
    float n = rintf(y);
    float f = y - n;                            // f in [-0.5, 0.5]
    float p = 1.525273380405984e-5f;
    p = fmaf(p, f, 1.540353039338161e-4f);
    p = fmaf(p, f, 1.333355814642844e-3f);
    p = fmaf(p, f, 9.618129107628477e-3f);
    p = fmaf(p, f, 5.550410866482158e-2f);
    p = fmaf(p, f, 2.402265069591007e-1f);
    p = fmaf(p, f, 6.931471805599453e-1f);
    p = fmaf(p, f, 1.0f);
    int e = (int)n;                             // |a|<=30 -> e in [-44,44], always valid
    return p * __int_as_float((e + 127) << 23);
}

// Flat index into d_out for dist(i, j), j != i.
// Output layout (flattened reference tuple):
//   [0]=loss [1]=accuracy [2]=pos_d [3]=neg_d [4 .. 4+N*7)=pos_dist [..]=neg_dist
__device__ __forceinline__ int out_index(int i, int j) {
    int lo = (i >> 3) << 3;                     // class block start
    unsigned rel = (unsigned)(j - lo);
    if (rel < 8u) {                             // positive (j != i guaranteed by caller)
        int p = j - lo - (j > i ? 1 : 0);
        return OFF_POS + i * NPOSD + p;
    }
    int p = (j < lo) ? j : (j - 8);
    return OFF_NEG + i * NNEGD + p;
}

// Block-wide sum over 256 threads (deterministic tree).
__device__ __forceinline__ float block_sum256(float v, float* buf) {
    int t = threadIdx.x;
#pragma unroll
    for (int d = 16; d > 0; d >>= 1) v += __shfl_down_sync(0xFFFFFFFFu, v, d);
    if ((t & 31) == 0) buf[t >> 5] = v;
    __syncthreads();
    if (t < 32) {
        float x = (t < 8) ? buf[t] : 0.0f;
#pragma unroll
        for (int d = 4; d > 0; d >>= 1) x += __shfl_down_sync(0xFFFFFFFFu, x, d);
        if (t == 0) buf[0] = x;
    }
    __syncthreads();
    float r = buf[0];
    __syncthreads();
    return r;
}

__device__ __forceinline__ float block_min256(float v, float* buf) {
    int t = threadIdx.x;
#pragma unroll
    for (int d = 16; d > 0; d >>= 1) v = fminf(v, __shfl_down_sync(0xFFFFFFFFu, v, d));
    if ((t & 31) == 0) buf[t >> 5] = v;
    __syncthreads();
    if (t < 32) {
        float x = (t < 8) ? buf[t] : __int_as_float(0x7f800000);
#pragma unroll
        for (int d = 4; d > 0; d >>= 1) x = fminf(x, __shfl_down_sync(0xFFFFFFFFu, x, d));
        if (t == 0) buf[0] = x;
    }
    __syncthreads();
    float r = buf[0];
    __syncthreads();
    return r;
}

// ---------------------------------------------------------------------------
// Kernel 1: row squared norms
// ---------------------------------------------------------------------------
__global__ __launch_bounds__(256) void sq_kernel(const float* __restrict__ X) {
    int i = blockIdx.x, t = threadIdx.x;
    const float4* row = (const float4*)(X + (size_t)i * DIM);
    float4 x = row[t];                           // DIM/4 == 256 == blockDim
    float s = fmaf(x.x, x.x, fmaf(x.y, x.y, fmaf(x.z, x.z, x.w * x.w)));
    __shared__ float rbuf[8];
    s = block_sum256(s, rbuf);
    if (t == 0) g_sq[i] = s;
}

// ---------------------------------------------------------------------------
// Kernel 2: symmetric SGEMM (f32x2 packed FMA) with fused dist epilogue that
// scatters directly into the pos/neg sections of d_out. Only upper-triangular
// block pairs are computed; off-diagonal tiles write both (i,j) and (j,i).
// ---------------------------------------------------------------------------
__global__ __launch_bounds__(256, 2) void gemm_dist_kernel(const float* __restrict__ X,
                                                           float* __restrict__ out) {
    __shared__ __align__(16) float As[BK][BM];
    __shared__ __align__(16) float Bs[BK][BN];

    // decode blockIdx -> (bi <= bj)
    int b = blockIdx.x;
    int bi = 0, rem = b;
    while (rem >= NB - bi) { rem -= NB - bi; bi++; }
    int bj = bi + rem;

    int t = threadIdx.x;
    int tx = t & 15, ty = t >> 4;

    unsigned long long acc[8][4];
#pragma unroll
    for (int m = 0; m < 8; m++)
#pragma unroll
        for (int n = 0; n < 4; n++) acc[m][n] = 0ull;

    const float* Ap = X + (size_t)bi * BM * DIM;
    const float* Bp = X + (size_t)bj * BM * DIM;
    int lr = t >> 2;            // 0..63
    int lc = (t & 3) << 2;      // 0,4,8,12

    for (int k0 = 0; k0 < DIM; k0 += BK) {
#pragma unroll
        for (int h = 0; h < 2; h++) {
            int r = lr + h * 64;
            float4 va = *(const float4*)(Ap + (size_t)r * DIM + k0 + lc);
            As[lc + 0][r] = va.x; As[lc + 1][r] = va.y;
            As[lc + 2][r] = va.z; As[lc + 3][r] = va.w;
            float4 vb = *(const float4*)(Bp + (size_t)r * DIM + k0 + lc);
            Bs[lc + 0][r] = vb.x; Bs[lc + 1][r] = vb.y;
            Bs[lc + 2][r] = vb.z; Bs[lc + 3][r] = vb.w;
        }
        __syncthreads();
#pragma unroll
        for (int kk = 0; kk < BK; kk++) {
            float4 a0 = *(const float4*)&As[kk][ty * 8];
            float4 a1 = *(const float4*)&As[kk][ty * 8 + 4];
            ulonglong2 b0 = *(const ulonglong2*)&Bs[kk][tx * 8];
            ulonglong2 b1 = *(const ulonglong2*)&Bs[kk][tx * 8 + 4];
            unsigned long long bp[4] = {b0.x, b0.y, b1.x, b1.y};
            float am[8] = {a0.x, a0.y, a0.z, a0.w, a1.x, a1.y, a1.z, a1.w};
#pragma unroll
            for (int m = 0; m < 8; m++) {
                unsigned long long ap = pack2(am[m], am[m]);
#pragma unroll
                for (int n = 0; n < 4; n++) fma2(acc[m][n], ap, bp[n]);
            }
        }
        __syncthreads();
    }

    int gi0 = bi * BM + ty * 8;
    int gj0 = bj * BN + tx * 8;
#pragma unroll
    for (int m = 0; m < 8; m++) {
        int gi = gi0 + m;
        float sqi = g_sq[gi];
#pragma unroll
        for (int n2 = 0; n2 < 4; n2++) {
            float c0, c1;
            unpack2(acc[m][n2], c0, c1);
            int gj = gj0 + n2 * 2;
            float d0 = sqrtf(fmaxf(sqi + g_sq[gj]     - 2.0f * c0, 1e-12f));
            float d1 = sqrtf(fmaxf(sqi + g_sq[gj + 1] - 2.0f * c1, 1e-12f));
            if (bi == bj) {
                if (gi != gj)     out[out_index(gi, gj)]     = d0;
                if (gi != gj + 1) out[out_index(gi, gj + 1)] = d1;
            } else {
                out[out_index(gi, gj)]     = d0;
                out[out_index(gj, gi)]     = d0;
                out[out_index(gi, gj + 1)] = d1;
                out[out_index(gj + 1, gi)] = d1;
            }
        }
    }
}

// ---------------------------------------------------------------------------
// Kernel 3: per-row exact 17th-smallest via bitwise radix select, then logits.
// One block (256 threads) per row; the row's 4095 dists live in registers.
// ---------------------------------------------------------------------------
__global__ __launch_bounds__(256) void row_select_kernel(const float* __restrict__ out) {
    int i = blockIdx.x;
    int t = threadIdx.x;
    const float* pos = out + OFF_POS + i * NPOSD;
    const float* neg = out + OFF_NEG + (size_t)i * NNEGD;

    float v[16];
    float psum = 0.0f, nsum = 0.0f;
    float minpos = __int_as_float(0x7f800000);
#pragma unroll
    for (int s = 0; s < 16; s++) {
        int idx = t + (s << 8);                  // 0..4095 ; 4095 is padding
        float val;
        if (idx < NPOSD) {
            val = pos[idx];
            psum += val;
            minpos = fminf(minpos, val);
        } else if (idx < NPOSD + NNEGD) {
            val = neg[idx - NPOSD];
            nsum += val;
        } else {
            val = __int_as_float(0x7f800000);    // +inf sorts last
        }
        v[s] = val;
    }

    // exact radix select: k-th smallest bit pattern (all values positive floats)
    __shared__ int hist[256];
    __shared__ int wsum[8];
    __shared__ int sel[2];
    unsigned prefix = 0u;
    int k = KSEL;
#pragma unroll
    for (int pass = 0; pass < 4; pass++) {
        int shift = 24 - pass * 8;
        hist[t] = 0;
        __syncthreads();
        unsigned pm = (pass == 0) ? 0u : (0xFFFFFFFFu << (shift + 8));
#pragma unroll
        for (int s = 0; s < 16; s++) {
            unsigned bbits = __float_as_uint(v[s]);
            if ((bbits & pm) == prefix) atomicAdd(&hist[(bbits >> shift) & 255u], 1);
        }
        __syncthreads();
        int cnt = hist[t];
        int x = cnt;
#pragma unroll
        for (int d2 = 1; d2 < 32; d2 <<= 1) {
            int y = __shfl_up_sync(0xFFFFFFFFu, x, d2);
            if ((t & 31) >= d2) x += y;
        }
        if ((t & 31) == 31) wsum[t >> 5] = x;
        __syncthreads();
        if (t < 8) {
            int y = wsum[t];
#pragma unroll
            for (int d2 = 1; d2 < 8; d2 <<= 1) {
                int z = __shfl_up_sync(0xFFu, y, d2);
                if (t >= d2) y += z;
            }
            wsum[t] = y;
        }
        __syncthreads();
        int incl = x + ((t >= 32) ? wsum[(t >> 5) - 1] : 0);
        int excl = incl - cnt;
        if (incl >= k && excl < k) { sel[0] = t; sel[1] = excl; }
        __syncthreads();
        prefix |= ((unsigned)sel[0]) << shift;
        k -= sel[1];
        __syncthreads();
    }
    float thr = __uint_as_float(prefix);         // exact 17th smallest

    // logits: strict d < thr, matching the reference
    float pe = 0.0f, ne = 0.0f;
#pragma unroll
    for (int s = 0; s < 16; s++) {
        int idx = t + (s << 8);
        float d = v[s];
        if (idx < NPOSD + NNEGD && d < thr) {
            float e = fast_exp(ALPHA_C * (1.0f - d));
            if (idx < NPOSD) pe += e; else ne += e;
        }
    }

    __shared__ float rbuf[8];
    pe     = block_sum256(pe, rbuf);
    ne     = block_sum256(ne, rbuf);
    psum   = block_sum256(psum, rbuf);
    nsum   = block_sum256(nsum, rbuf);
    minpos = block_min256(minpos, rbuf);

    if (t == 0) {
        float pl = (minpos < thr) ? pe : fast_exp(ALPHA_C * (1.0f - minpos));
        float loss = logf(pl + ne) - logf(pl);
        g_loss[i] = loss;
        g_psum[i] = psum;
        g_nsum[i] = nsum;
    }
}

// ---------------------------------------------------------------------------
// Kernel 4: deterministic final reduction -> 4 scalars
// ---------------------------------------------------------------------------
__global__ __launch_bounds__(256) void final_kernel(float* __restrict__ out) {
    int t = threadIdx.x;
    float ls = 0.0f, ac = 0.0f, ps = 0.0f, ns = 0.0f;
    for (int j = t; j < NPTS; j += 256) {
        float l = g_loss[j];
        ls += l;
        ac += (l < 0.6f) ? 1.0f : 0.0f;
        ps += g_psum[j];
        ns += g_nsum[j];
    }
    __shared__ float rbuf[8];
    ls = block_sum256(ls, rbuf);
    ac = block_sum256(ac, rbuf);
    ps = block_sum256(ps, rbuf);
    ns = block_sum256(ns, rbuf);
    if (t == 0) {
        out[0] = ls / (float)NPTS;
        out[1] = ac / (float)NPTS;
        out[2] = ps / ((float)NPTS * (float)NPOSD);
        out[3] = ns / ((float)NPTS * (float)NNEGD);
    }
}

// ---------------------------------------------------------------------------
// Launch
// ---------------------------------------------------------------------------
extern "C" void kernel_launch(void* const* d_in, const int* in_sizes, int n_in,
                              void* d_out, int out_size) {
    const float* X = (const float*)d_in[0];
    float* out = (float*)d_out;
    (void)in_sizes; (void)n_in; (void)out_size;

    sq_kernel<<<NPTS, 256>>>(X);
    gemm_dist_kernel<<<NB * (NB + 1) / 2, 256>>>(X, out);
    row_select_kernel<<<NPTS, 256>>>(out);
    final_kernel<<<1, 256>>>(out);
}

// round 4
// speedup vs baseline: 1.6827x; 1.6821x over previous
#include <cuda_runtime.h>
#include <cuda_bf16.h>
#include <math.h>
#include <stdint.h>

#define NPTS 4096
#define DIM  1024
#define NPOSD 7
#define NNEGD 4088
#define KSEL 17
#define ALPHA_C 30.0f
#define OFF_POS 4
#define OFF_NEG (4 + NPTS * NPOSD)

// GEMM config: tile 128x128, K=3072 (bf16 2-way split, K-packed), BK=32
#define NB 32                 // 4096/128 row blocks
#define BK 32
#define KITERS 96             // 3072/32
#define STAGES 4
#define LDM 40                // smem row stride in bf16 elems (80B, conflict-free ldmatrix)
#define STAGE_A (128 * LDM * 2)          // 10240 B
#define STAGE_BYTES (2 * STAGE_A)        // 20480 B
#define GEMM_SMEM (STAGES * STAGE_BYTES) // 81920 B

__device__ __nv_bfloat16 g_s1[NPTS * DIM];  // bf16 main split, row-major
__device__ __nv_bfloat16 g_s2[NPTS * DIM];  // bf16 residual split
__device__ float g_sq[NPTS];
__device__ float g_loss[NPTS];
__device__ float g_psum[NPTS];
__device__ float g_nsum[NPTS];
__device__ int   g_ctr;

// ---------------------------------------------------------------------------
__device__ __forceinline__ uint32_t smem_u32(const void* p) {
    uint32_t a;
    asm("{ .reg .u64 t; cvta.to.shared.u64 t, %1; cvt.u32.u64 %0, t; }" : "=r"(a) : "l"(p));
    return a;
}
__device__ __forceinline__ void cp_async16(uint32_t dst, const void* src) {
    asm volatile("cp.async.cg.shared.global [%0], [%1], 16;" :: "r"(dst), "l"(src));
}
__device__ __forceinline__ void cp_commit() {
    asm volatile("cp.async.commit_group;");
}
template <int N>
__device__ __forceinline__ void cp_wait() {
    asm volatile("cp.async.wait_group %0;" :: "n"(N));
}
__device__ __forceinline__ void ldsm4(uint32_t* r, uint32_t addr) {
    asm volatile("ldmatrix.sync.aligned.m8n8.x4.shared.b16 {%0,%1,%2,%3}, [%4];"
                 : "=r"(r[0]), "=r"(r[1]), "=r"(r[2]), "=r"(r[3]) : "r"(addr));
}
__device__ __forceinline__ void mma16816(float* d, const uint32_t* a,
                                         uint32_t b0, uint32_t b1) {
    asm volatile("mma.sync.aligned.m16n8k16.row.col.f32.bf16.bf16.f32 "
                 "{%0,%1,%2,%3}, {%4,%5,%6,%7}, {%8,%9}, {%0,%1,%2,%3};"
                 : "+f"(d[0]), "+f"(d[1]), "+f"(d[2]), "+f"(d[3])
                 : "r"(a[0]), "r"(a[1]), "r"(a[2]), "r"(a[3]), "r"(b0), "r"(b1));
}

// ---------------------------------------------------------------------------
__device__ __forceinline__ float fast_exp(float a) {
    float y = a * 1.4426950408889634f;
    float n = rintf(y);
    float f = y - n;
    float p = 1.525273380405984e-5f;
    p = fmaf(p, f, 1.540353039338161e-4f);
    p = fmaf(p, f, 1.333355814642844e-3f);
    p = fmaf(p, f, 9.618129107628477e-3f);
    p = fmaf(p, f, 5.550410866482158e-2f);
    p = fmaf(p, f, 2.402265069591007e-1f);
    p = fmaf(p, f, 6.931471805599453e-1f);
    p = fmaf(p, f, 1.0f);
    int e = (int)n;
    return p * __int_as_float((e + 127) << 23);
}
__device__ __forceinline__ int out_index(int i, int j) {
    int lo = (i >> 3) << 3;
    unsigned rel = (unsigned)(j - lo);
    if (rel < 8u) {
        int p = j - lo - (j > i ? 1 : 0);
        return OFF_POS + i * NPOSD + p;
    }
    int p = (j < lo) ? j : (j - 8);
    return OFF_NEG + i * NNEGD + p;
}
__device__ __forceinline__ float block_sum256(float v, float* buf) {
    int t = threadIdx.x;
#pragma unroll
    for (int d = 16; d > 0; d >>= 1) v += __shfl_down_sync(0xFFFFFFFFu, v, d);
    if ((t & 31) == 0) buf[t >> 5] = v;
    __syncthreads();
    if (t < 32) {
        float x = (t < 8) ? buf[t] : 0.0f;
#pragma unroll
        for (int d = 4; d > 0; d >>= 1) x += __shfl_down_sync(0xFFFFFFFFu, x, d);
        if (t == 0) buf[0] = x;
    }
    __syncthreads();
    float r = buf[0];
    __syncthreads();
    return r;
}
__device__ __forceinline__ float block_min256(float v, float* buf) {
    int t = threadIdx.x;
#pragma unroll
    for (int d = 16; d > 0; d >>= 1) v = fminf(v, __shfl_down_sync(0xFFFFFFFFu, v, d));
    if ((t & 31) == 0) buf[t >> 5] = v;
    __syncthreads();
    if (t < 32) {
        float x = (t < 8) ? buf[t] : __int_as_float(0x7f800000);
#pragma unroll
        for (int d = 4; d > 0; d >>= 1) x = fminf(x, __shfl_down_sync(0xFFFFFFFFu, x, d));
        if (t == 0) buf[0] = x;
    }
    __syncthreads();
    float r = buf[0];
    __syncthreads();
    return r;
}

// ---------------------------------------------------------------------------
// Kernel 1: row squared norms (+ counter reset)
// ---------------------------------------------------------------------------
__global__ __launch_bounds__(256) void sq_kernel(const float* __restrict__ X) {
    int i = blockIdx.x, t = threadIdx.x;
    if (i == 0 && t == 0) g_ctr = 0;
    const float4* row = (const float4*)(X + (size_t)i * DIM);
    float4 x = row[t];
    float s = fmaf(x.x, x.x, fmaf(x.y, x.y, fmaf(x.z, x.z, x.w * x.w)));
    __shared__ float rbuf[8];
    s = block_sum256(s, rbuf);
    if (t == 0) g_sq[i] = s;
}

// ---------------------------------------------------------------------------
// Kernel 2: bf16 2-way split, row-major
// ---------------------------------------------------------------------------
__global__ __launch_bounds__(128) void prep_kernel(const float* __restrict__ X) {
    int i = blockIdx.x, t = threadIdx.x;
    const float4* row = (const float4*)(X + (size_t)i * DIM);
    float4 x0 = row[t * 2], x1 = row[t * 2 + 1];
    float xs[8] = {x0.x, x0.y, x0.z, x0.w, x1.x, x1.y, x1.z, x1.w};
    unsigned int w1[4], w2[4];
#pragma unroll
    for (int e = 0; e < 4; e++) {
        float xa = xs[2 * e], xb = xs[2 * e + 1];
        __nv_bfloat16 ha = __float2bfloat16(xa);
        __nv_bfloat16 hb = __float2bfloat16(xb);
        __nv_bfloat16 ra = __float2bfloat16(xa - __bfloat162float(ha));
        __nv_bfloat16 rb = __float2bfloat16(xb - __bfloat162float(hb));
        w1[e] = (unsigned)__bfloat16_as_ushort(ha) | ((unsigned)__bfloat16_as_ushort(hb) << 16);
        w2[e] = (unsigned)__bfloat16_as_ushort(ra) | ((unsigned)__bfloat16_as_ushort(rb) << 16);
    }
    size_t off = (size_t)i * DIM + t * 8;
    *(uint4*)(g_s1 + off) = make_uint4(w1[0], w1[1], w1[2], w1[3]);
    *(uint4*)(g_s2 + off) = make_uint4(w2[0], w2[1], w2[2], w2[3]);
}

// ---------------------------------------------------------------------------
// Kernel 3: bf16 HMMA GEMM (mma.sync m16n8k16), triangular 128x128 tiles,
// K=3072 packed split, 4-stage cp.async pipeline, fused dist epilogue.
// ---------------------------------------------------------------------------
__global__ __launch_bounds__(256) void gemm_dist_kernel(float* __restrict__ out) {
    extern __shared__ __align__(16) unsigned char smem_raw[];
    uint32_t sbase = smem_u32(smem_raw);

    // decode blockIdx -> (bi <= bj) over 128-row blocks
    int b = blockIdx.x;
    int bi = 0, rem = b;
    while (rem >= NB - bi) { rem -= NB - bi; bi++; }
    int bj = bi + rem;

    int tid = threadIdx.x;
    int wid = tid >> 5, lane = tid & 31;
    int wm = wid >> 2, wn = wid & 3;         // warp grid 2 x 4
    int mbase = wm * 64, nbase = wn * 32;

    // K-seg -> split-source selection: A: [s1,s1,s2], B: [s1,s2,s1]
    const __nv_bfloat16* Asrc[3] = {g_s1, g_s1, g_s2};
    const __nv_bfloat16* Bsrc[3] = {g_s1, g_s2, g_s1};

    // cp.async mapping: thread t loads 2x16B of one half-row for A and B.
    int ldrow = tid >> 1;                    // 0..127
    int ldhalf = tid & 1;                    // half-row: chunks 2h, 2h+1

    float acc[4][4][4];
#pragma unroll
    for (int mt = 0; mt < 4; mt++)
#pragma unroll
        for (int nt = 0; nt < 4; nt++)
#pragma unroll
            for (int e = 0; e < 4; e++) acc[mt][nt][e] = 0.0f;

    auto issue_load = [&](int stage, int c) {
        int seg = c >> 5;                    // 0..2
        int kk = (c & 31) * BK;              // k offset within 1024
        uint32_t sA = sbase + stage * STAGE_BYTES;
        uint32_t sB = sA + STAGE_A;
        const __nv_bfloat16* ga = Asrc[seg] + (size_t)(bi * 128 + ldrow) * DIM + kk + ldhalf * 16;
        const __nv_bfloat16* gb = Bsrc[seg] + (size_t)(bj * 128 + ldrow) * DIM + kk + ldhalf * 16;
        uint32_t dA = sA + (uint32_t)(ldrow * LDM + ldhalf * 16) * 2;
        uint32_t dB = sB + (uint32_t)(ldrow * LDM + ldhalf * 16) * 2;
        cp_async16(dA, ga);
        cp_async16(dA + 16, (const char*)ga + 16);
        cp_async16(dB, gb);
        cp_async16(dB + 16, (const char*)gb + 16);
    };

    // prologue: 3 stages
#pragma unroll
    for (int s = 0; s < STAGES - 1; s++) { issue_load(s, s); cp_commit(); }

    int lrow = lane & 15, lcolsel = (lane >> 4) * 8;

    for (int c = 0; c < KITERS; c++) {
        cp_wait<STAGES - 2>();
        __syncthreads();
        int st = c & (STAGES - 1);
        uint32_t sA = sbase + st * STAGE_BYTES;
        uint32_t sB = sA + STAGE_A;
#pragma unroll
        for (int ks = 0; ks < 2; ks++) {
            uint32_t af[4][4], bf[2][4];
#pragma unroll
            for (int mt = 0; mt < 4; mt++)
                ldsm4(af[mt], sA + (uint32_t)((mbase + mt * 16 + lrow) * LDM
                                              + ks * 16 + lcolsel) * 2);
#pragma unroll
            for (int nb2 = 0; nb2 < 2; nb2++)
                ldsm4(bf[nb2], sB + (uint32_t)((nbase + nb2 * 16 + lrow) * LDM
                                               + ks * 16 + lcolsel) * 2);
#pragma unroll
            for (int mt = 0; mt < 4; mt++)
#pragma unroll
                for (int nt = 0; nt < 4; nt++)
                    mma16816(acc[mt][nt], af[mt], bf[nt >> 1][nt & 1],
                             bf[nt >> 1][(nt & 1) + 2]);
        }
        __syncthreads();
        if (c + STAGES - 1 < KITERS) issue_load((c + STAGES - 1) & (STAGES - 1),
                                                c + STAGES - 1);
        cp_commit();
    }

    // ---- epilogue: dist + scatter (direct + mirror) ----
    bool diag = (bi == bj);
    int r_in = lane >> 2, c_in = (lane & 3) * 2;
#pragma unroll
    for (int mt = 0; mt < 4; mt++) {
        int gr0 = bi * 128 + mbase + mt * 16 + r_in;
        float sq_r0 = __ldg(&g_sq[gr0]);
        float sq_r1 = __ldg(&g_sq[gr0 + 8]);
#pragma unroll
        for (int nt = 0; nt < 4; nt++) {
            int gc0 = bj * 128 + nbase + nt * 8 + c_in;
            float sq_c0 = __ldg(&g_sq[gc0]);
            float sq_c1 = __ldg(&g_sq[gc0 + 1]);
            float d00 = sqrtf(fmaxf(sq_r0 + sq_c0 - 2.0f * acc[mt][nt][0], 1e-12f));
            float d01 = sqrtf(fmaxf(sq_r0 + sq_c1 - 2.0f * acc[mt][nt][1], 1e-12f));
            float d10 = sqrtf(fmaxf(sq_r1 + sq_c0 - 2.0f * acc[mt][nt][2], 1e-12f));
            float d11 = sqrtf(fmaxf(sq_r1 + sq_c1 - 2.0f * acc[mt][nt][3], 1e-12f));
            if (diag) {
                if (gr0 != gc0)         out[out_index(gr0, gc0)] = d00;
                if (gr0 != gc0 + 1)     out[out_index(gr0, gc0 + 1)] = d01;
                if (gr0 + 8 != gc0)     out[out_index(gr0 + 8, gc0)] = d10;
                if (gr0 + 8 != gc0 + 1) out[out_index(gr0 + 8, gc0 + 1)] = d11;
            } else {
                out[out_index(gr0, gc0)] = d00;
                out[out_index(gc0, gr0)] = d00;
                out[out_index(gr0, gc0 + 1)] = d01;
                out[out_index(gc0 + 1, gr0)] = d01;
                out[out_index(gr0 + 8, gc0)] = d10;
                out[out_index(gc0, gr0 + 8)] = d10;
                out[out_index(gr0 + 8, gc0 + 1)] = d11;
                out[out_index(gc0 + 1, gr0 + 8)] = d11;
            }
        }
    }
}

// ---------------------------------------------------------------------------
// Kernel 4: per-row exact 17th-smallest (radix select) + logits; last block
// does the final deterministic reduction into out[0..3].
// ---------------------------------------------------------------------------
__global__ __launch_bounds__(256) void row_select_kernel(float* __restrict__ out) {
    int i = blockIdx.x;
    int t = threadIdx.x;
    const float* pos = out + OFF_POS + i * NPOSD;
    const float* neg = out + OFF_NEG + (size_t)i * NNEGD;

    float v[16];
    float psum = 0.0f, nsum = 0.0f;
    float minpos = __int_as_float(0x7f800000);
#pragma unroll
    for (int s = 0; s < 16; s++) {
        int idx = t + (s << 8);
        float val;
        if (idx < NPOSD) {
            val = pos[idx];
            psum += val;
            minpos = fminf(minpos, val);
        } else if (idx < NPOSD + NNEGD) {
            val = neg[idx - NPOSD];
            nsum += val;
        } else {
            val = __int_as_float(0x7f800000);
        }
        v[s] = val;
    }

    __shared__ int hist[256];
    __shared__ int wsum[8];
    __shared__ int sel[2];
    unsigned prefix = 0u;
    int k = KSEL;
#pragma unroll
    for (int pass = 0; pass < 4; pass++) {
        int shift = 24 - pass * 8;
        hist[t] = 0;
        __syncthreads();
        unsigned pm = (pass == 0) ? 0u : (0xFFFFFFFFu << (shift + 8));
#pragma unroll
        for (int s = 0; s < 16; s++) {
            unsigned bb = __float_as_uint(v[s]);
            if ((bb & pm) == prefix) atomicAdd(&hist[(bb >> shift) & 255u], 1);
        }
        __syncthreads();
        int cnt = hist[t];
        int x = cnt;
#pragma unroll
        for (int d2 = 1; d2 < 32; d2 <<= 1) {
            int y = __shfl_up_sync(0xFFFFFFFFu, x, d2);
            if ((t & 31) >= d2) x += y;
        }
        if ((t & 31) == 31) wsum[t >> 5] = x;
        __syncthreads();
        if (t < 8) {
            int y = wsum[t];
#pragma unroll
            for (int d2 = 1; d2 < 8; d2 <<= 1) {
                int z = __shfl_up_sync(0xFFu, y, d2);
                if (t >= d2) y += z;
            }
            wsum[t] = y;
        }
        __syncthreads();
        int incl = x + ((t >= 32) ? wsum[(t >> 5) - 1] : 0);
        int excl = incl - cnt;
        if (incl >= k && excl < k) { sel[0] = t; sel[1] = excl; }
        __syncthreads();
        prefix |= ((unsigned)sel[0]) << shift;
        k -= sel[1];
        __syncthreads();
    }
    float thr = __uint_as_float(prefix);

    float pe = 0.0f, ne = 0.0f;
#pragma unroll
    for (int s = 0; s < 16; s++) {
        int idx = t + (s << 8);
        float d = v[s];
        if (idx < NPOSD + NNEGD && d < thr) {
            float e = fast_exp(ALPHA_C * (1.0f - d));
            if (idx < NPOSD) pe += e; else ne += e;
        }
    }

    __shared__ float rbuf[8];
    pe     = block_sum256(pe, rbuf);
    ne     = block_sum256(ne, rbuf);
    psum   = block_sum256(psum, rbuf);
    nsum   = block_sum256(nsum, rbuf);
    minpos = block_min256(minpos, rbuf);

    if (t == 0) {
        float pl = (minpos < thr) ? pe : fast_exp(ALPHA_C * (1.0f - minpos));
        g_loss[i] = logf(pl + ne) - logf(pl);
        g_psum[i] = psum;
        g_nsum[i] = nsum;
    }

    __threadfence();
    __shared__ int lastflag;
    if (t == 0) lastflag = (atomicAdd(&g_ctr, 1) == NPTS - 1) ? 1 : 0;
    __syncthreads();
    if (lastflag) {
        float ls = 0.0f, ac = 0.0f, ps = 0.0f, ns = 0.0f;
        for (int j = t; j < NPTS; j += 256) {
            float l = g_loss[j];
            ls += l;
            ac += (l < 0.6f) ? 1.0f : 0.0f;
            ps += g_psum[j];
            ns += g_nsum[j];
        }
        ls = block_sum256(ls, rbuf);
        ac = block_sum256(ac, rbuf);
        ps = block_sum256(ps, rbuf);
        ns = block_sum256(ns, rbuf);
        if (t == 0) {
            out[0] = ls / (float)NPTS;
            out[1] = ac / (float)NPTS;
            out[2] = ps / ((float)NPTS * (float)NPOSD);
            out[3] = ns / ((float)NPTS * (float)NNEGD);
        }
    }
}

// ---------------------------------------------------------------------------
extern "C" void kernel_launch(void* const* d_in, const int* in_sizes, int n_in,
                              void* d_out, int out_size) {
    const float* X = (const float*)d_in[0];
    float* out = (float*)d_out;
    (void)in_sizes; (void)n_in; (void)out_size;

    cudaFuncSetAttribute(gemm_dist_kernel, cudaFuncAttributeMaxDynamicSharedMemorySize,
                         GEMM_SMEM);
    sq_kernel<<<NPTS, 256>>>(X);
    prep_kernel<<<NPTS, 128>>>(X);
    gemm_dist_kernel<<<NB * (NB + 1) / 2, 256, GEMM_SMEM>>>(out);
    row_select_kernel<<<NPTS, 256>>>(out);
}